// round 1
// baseline (speedup 1.0000x reference)
#include <cuda_runtime.h>
#include <math.h>

#define NBLK 128
#define NTHR 256

#define Bn 64
#define Hn 512
#define Sn 512
#define BH (Bn*Hn)         // 32768

// output section offsets (in floats)
//   hidden_seq (B,S,H) | h_mus (B,S+1,H) | h_stds | c_mus | c_stds | h_T (1,B,H) | c_T
#define O_HID   0ull
#define O_HMU   16777216ull
#define O_HSTD  33587200ull
#define O_CMU   50397184ull
#define O_CSTD  67207168ull
#define O_HT    84017152ull
#define O_CT    84049920ull

// persistent state (sampled carries and pre-sample activations)
__device__ float g_h[BH], g_c[BH], g_hn[BH], g_cn[BH];
__device__ unsigned g_cnt = 0;
__device__ volatile unsigned g_gen = 0;

__device__ __forceinline__ void grid_bar() {
    __syncthreads();
    if (threadIdx.x == 0) {
        __threadfence();
        unsigned gen = g_gen;
        if (atomicAdd(&g_cnt, 1u) == NBLK - 1) {
            g_cnt = 0;
            __threadfence();
            g_gen = gen + 1;
        } else {
            while (g_gen == gen) { }
            __threadfence();
        }
    }
    __syncthreads();
}

__device__ __forceinline__ float sigm(float v) { return 1.0f / (1.0f + expf(-v)); }
__device__ __forceinline__ float softplus(float v) {
    // matches jax.nn.softplus = logaddexp(v, 0)
    return fmaxf(v, 0.0f) + log1pf(expf(-fabsf(v)));
}

__global__ __launch_bounds__(NTHR, 1)
void rglstm(const float* __restrict__ x,
            const float* __restrict__ W_ih, const float* __restrict__ W_hh,
            const float* __restrict__ b_ih, const float* __restrict__ b_hh,
            const float* __restrict__ W_hg, const float* __restrict__ W_cg,
            const float* __restrict__ eps_h, const float* __restrict__ eps_c,
            float* __restrict__ out)
{
    extern __shared__ float smem[];
    float* sW1 = smem;                 // [1024][16]  stage-1 weight slice (persistent)
    float* sW2 = smem + 16384;         // [512][16]   stage-2 weight slice (persistent)
    float* As  = smem + 16384 + 8192;  // 2 x [16][68] A-operand tiles (double buffer)

    const int tid  = threadIdx.x;
    const int cb   = blockIdx.x;
    const int col  = tid & 15;     // output column within the 16-wide tile
    const int rblk = tid >> 4;     // row block: rows rblk*4 .. rblk*4+3
    const int lane = tid & 31;
    const int bA   = tid >> 2;     // A-tile load: row
    const int kkb  = (tid & 3) << 2; // A-tile load: k offset (float4)

    const int n0_1 = cb << 2;               // stage 1: this CTA owns hidden cols n0_1..n0_1+3 (x4 gates)
    const bool isH = (cb < 64);
    const int n0_2 = (cb & 63) << 3;        // stage 2: 8 hidden cols

    // ---- persistent weight slices into SMEM ----
    for (int i = tid; i < 16 * 1024; i += NTHR) {
        int c2 = i >> 10, k = i & 1023;
        int gcol = ((c2 >> 2) << 9) + n0_1 + (c2 & 3);     // gate*512 + n
        float w = (k < Hn) ? W_ih[gcol * Hn + k] : W_hh[gcol * Hn + (k - Hn)];
        sW1[k * 16 + c2] = w;
    }
    const float* Wg = isH ? W_hg : W_cg;
    for (int i = tid; i < 16 * 512; i += NTHR) {
        int k = i >> 4, c2 = i & 15;
        int pcol = (c2 < 8) ? (n0_2 + c2) : (Hn + n0_2 + c2 - 8);
        sW2[k * 16 + c2] = Wg[k * (2 * Hn) + pcol];
    }

    const int gcol1 = ((col >> 2) << 9) + n0_1 + (col & 3);
    const float bias1 = b_ih[gcol1] + b_hh[gcol1];

    // ---- t=0: z=0 -> p=0 -> mu=1e-6, std=softplus(0)=ln2 ----
    {
        const float LN2 = 0.693147180559945309f;
        int i = cb * NTHR + tid;            // exactly 0..32767
        g_h[i] = fmaf(eps_h[i], LN2, 1e-6f);
        g_c[i] = fmaf(eps_c[i], LN2, 1e-6f);
        int b = i >> 9, n = i & 511;
        size_t o = (size_t)b * 262656 + n;  // (b, 0, n) of (B, S+1, H)
        out[O_HMU  + o] = 1e-6f;
        out[O_HSTD + o] = LN2;
        out[O_CMU  + o] = 1e-6f;
        out[O_CSTD + o] = LN2;
    }
    grid_bar();

    const float* Asrc   = isH ? g_hn  : g_cn;
    float*       Sdst   = isH ? g_h   : g_c;
    const float* epsP   = isH ? eps_h : eps_c;
    const size_t muBase = isH ? O_HMU  : O_CMU;
    const size_t sdBase = isH ? O_HSTD : O_CSTD;
    const size_t tBase  = isH ? O_HT   : O_CT;

    for (int s = 0; s < Sn; ++s) {
        // ================= stage 1: gates = [x_t | h] @ [W_ih;W_hh]^T =================
        const float* xrow = x + ((size_t)bA * Sn + s) * 512;
        auto ldA1 = [&](int kc) -> float4 {
            int kg = (kc << 4) + kkb;
            if (kg < Hn) return __ldg((const float4*)(xrow + kg));
            return __ldcg((const float4*)(g_h + bA * 512 + (kg - Hn)));
        };
        float a0 = 0.f, a1 = 0.f, a2 = 0.f, a3 = 0.f;
        {
            float4 pv = ldA1(0);
            As[(kkb+0)*68 + bA] = pv.x; As[(kkb+1)*68 + bA] = pv.y;
            As[(kkb+2)*68 + bA] = pv.z; As[(kkb+3)*68 + bA] = pv.w;
        }
        float4 pn = ldA1(1);
        __syncthreads();
        for (int kc = 0; kc < 64; ++kc) {
            if (kc + 1 < 64) {
                float* d1 = As + ((kc + 1) & 1) * 1088;
                d1[(kkb+0)*68 + bA] = pn.x; d1[(kkb+1)*68 + bA] = pn.y;
                d1[(kkb+2)*68 + bA] = pn.z; d1[(kkb+3)*68 + bA] = pn.w;
            }
            if (kc + 2 < 64) pn = ldA1(kc + 2);
            const float* buf = As + (kc & 1) * 1088 + (rblk << 2);
            const float* wp  = sW1 + (kc << 8) + col;
            #pragma unroll
            for (int kk = 0; kk < 16; ++kk) {
                float4 av = *(const float4*)(buf + kk * 68);
                float  wv = wp[kk * 16];
                a0 = fmaf(av.x, wv, a0); a1 = fmaf(av.y, wv, a1);
                a2 = fmaf(av.z, wv, a2); a3 = fmaf(av.w, wv, a3);
            }
            __syncthreads();
        }
        // epilogue: gather i/f/g/o across lanes, LSTM pointwise
        {
            float gv[4] = { a0 + bias1, a1 + bias1, a2 + bias1, a3 + bias1 };
            int base = lane & 19;          // keep n bits (0,1) + rblk-parity bit (4)
            #pragma unroll
            for (int r = 0; r < 4; ++r) {
                float vi = __shfl_sync(0xffffffffu, gv[r], base);
                float vf = __shfl_sync(0xffffffffu, gv[r], base + 4);
                float vg = __shfl_sync(0xffffffffu, gv[r], base + 8);
                float vo = __shfl_sync(0xffffffffu, gv[r], base + 12);
                if ((col >> 2) == 0) {     // one writer lane per n
                    int b = (rblk << 2) + r;
                    int n = n0_1 + (col & 3);
                    float co = __ldcg(&g_c[b * 512 + n]);
                    float cv = sigm(vf) * co + sigm(vi) * tanhf(vg);
                    float hv = sigm(vo) * tanhf(cv);
                    __stcg(&g_cn[b * 512 + n], cv);
                    __stcg(&g_hn[b * 512 + n], hv);
                }
            }
        }
        grid_bar();

        // ================= stage 2: p = v @ Wg, sample =================
        auto ldA2 = [&](int kc) -> float4 {
            return __ldcg((const float4*)(Asrc + bA * 512 + (kc << 4) + kkb));
        };
        float q0 = 0.f, q1 = 0.f, q2 = 0.f, q3 = 0.f;
        {
            float4 pv = ldA2(0);
            As[(kkb+0)*68 + bA] = pv.x; As[(kkb+1)*68 + bA] = pv.y;
            As[(kkb+2)*68 + bA] = pv.z; As[(kkb+3)*68 + bA] = pv.w;
        }
        float4 pm = ldA2(1);
        __syncthreads();
        for (int kc = 0; kc < 32; ++kc) {
            if (kc + 1 < 32) {
                float* d1 = As + ((kc + 1) & 1) * 1088;
                d1[(kkb+0)*68 + bA] = pm.x; d1[(kkb+1)*68 + bA] = pm.y;
                d1[(kkb+2)*68 + bA] = pm.z; d1[(kkb+3)*68 + bA] = pm.w;
            }
            if (kc + 2 < 32) pm = ldA2(kc + 2);
            const float* buf = As + (kc & 1) * 1088 + (rblk << 2);
            const float* wp  = sW2 + (kc << 8) + col;
            #pragma unroll
            for (int kk = 0; kk < 16; ++kk) {
                float4 av = *(const float4*)(buf + kk * 68);
                float  wv = wp[kk * 16];
                q0 = fmaf(av.x, wv, q0); q1 = fmaf(av.y, wv, q1);
                q2 = fmaf(av.z, wv, q2); q3 = fmaf(av.w, wv, q3);
            }
            __syncthreads();
        }
        // epilogue: pair (mu, pre-std) lanes, sample, write outputs + carry
        {
            float acc2[4] = { q0, q1, q2, q3 };
            #pragma unroll
            for (int r = 0; r < 4; ++r) {
                float p   = acc2[r];
                float oth = __shfl_xor_sync(0xffffffffu, p, 8);
                bool mul  = (col & 8) == 0;
                float pmu = mul ? p : oth;
                float pst = mul ? oth : p;
                float mu  = fminf(fmaxf(pmu, 1e-6f), 1e6f);
                float sd  = fmaxf(softplus(pst), 1e-6f);
                int b = (rblk << 2) + r;
                int n = n0_2 + (col & 7);
                float e   = epsP[(size_t)(s + 1) * BH + b * 512 + n];
                float smp = fmaf(e, sd, mu);
                size_t o = (size_t)b * 262656 + (size_t)(s + 1) * 512 + n;
                if (mul) {
                    __stcg(&Sdst[b * 512 + n], smp);
                    out[muBase + o] = mu;
                    if (s == Sn - 1) out[tBase + (size_t)b * 512 + n] = smp;
                } else {
                    out[sdBase + o] = sd;
                    if (isH) out[(size_t)b * 262144 + (size_t)s * 512 + n] = smp;
                }
            }
        }
        grid_bar();
    }
}

#define SMEM_BYTES ((16384 + 8192 + 2 * 1088) * 4)

extern "C" void kernel_launch(void* const* d_in, const int* in_sizes, int n_in,
                              void* d_out, int out_size) {
    (void)in_sizes; (void)n_in; (void)out_size;
    const float* x    = (const float*)d_in[0];
    const float* W_ih = (const float*)d_in[1];
    const float* W_hh = (const float*)d_in[2];
    const float* b_ih = (const float*)d_in[3];
    const float* b_hh = (const float*)d_in[4];
    const float* W_hg = (const float*)d_in[5];
    const float* W_cg = (const float*)d_in[6];
    const float* eps_h = (const float*)d_in[7];
    const float* eps_c = (const float*)d_in[8];
    float* out = (float*)d_out;

    cudaFuncSetAttribute(rglstm, cudaFuncAttributeMaxDynamicSharedMemorySize, SMEM_BYTES);
    rglstm<<<NBLK, NTHR, SMEM_BYTES>>>(x, W_ih, W_hh, b_ih, b_hh,
                                       W_hg, W_cg, eps_h, eps_c, out);
}

// round 2
// speedup vs baseline: 1.5631x; 1.5631x over previous
#include <cuda_runtime.h>
#include <math.h>

#define NBLK 128
#define NTHR 256

#define Bn 64
#define Hn 512
#define Sn 512
#define BH (Bn*Hn)         // 32768

// output section offsets (in floats)
#define O_HID   0ull
#define O_HMU   16777216ull
#define O_HSTD  33587200ull
#define O_CMU   50397184ull
#define O_CSTD  67207168ull
#define O_HT    84017152ull
#define O_CT    84049920ull

// persistent state, all [n][b] transposed (b contiguous)
__device__ float g_h[BH], g_c[BH], g_hn[BH], g_cn[BH];
__device__ float g_xT[(size_t)Sn * 512 * 64];   // [s][k][b]  64MB
__device__ unsigned g_cnt = 0;
__device__ volatile unsigned g_gen = 0;

__device__ __forceinline__ void grid_bar() {
    __syncthreads();
    if (threadIdx.x == 0) {
        __threadfence();
        unsigned gen = g_gen;
        if (atomicAdd(&g_cnt, 1u) == NBLK - 1) {
            g_cnt = 0;
            __threadfence();
            g_gen = gen + 1;
        } else {
            while (g_gen == gen) { }
            __threadfence();
        }
    }
    __syncthreads();
}

__device__ __forceinline__ float sigm(float v) { return 1.0f / (1.0f + expf(-v)); }
__device__ __forceinline__ float softplus(float v) {
    return fmaxf(v, 0.0f) + log1pf(expf(-fabsf(v)));
}

// ---- packed f32x2 helpers (Blackwell FFMA2, PTX-only) ----
__device__ __forceinline__ unsigned long long pack2(float a, float b) {
    unsigned long long r;
    asm("mov.b64 %0, {%1, %2};" : "=l"(r) : "f"(a), "f"(b));
    return r;
}
__device__ __forceinline__ unsigned long long fma2(unsigned long long a,
                                                   unsigned long long b,
                                                   unsigned long long c) {
    unsigned long long d;
    asm("fma.rn.f32x2 %0, %1, %2, %3;" : "=l"(d) : "l"(a), "l"(b), "l"(c));
    return d;
}

// one-time x transpose: x[b][s][k] -> g_xT[s][k][b]
__global__ void xT_kernel(const float* __restrict__ x) {
    __shared__ float t[32][33];
    int s = blockIdx.x, k0 = blockIdx.y << 5, b0 = blockIdx.z << 5;
    int tx = threadIdx.x, ty = threadIdx.y;
    for (int bb = ty; bb < 32; bb += 8)
        t[bb][tx] = x[((size_t)(b0 + bb) * Sn + s) * 512 + k0 + tx];
    __syncthreads();
    for (int kk = ty; kk < 32; kk += 8)
        g_xT[((size_t)s * 512 + k0 + kk) * 64 + b0 + tx] = t[tx][kk];
}

// smem (floats): sW1 16384 | sW2 8192 | As 2*4352 | red 4*1088
#define SM_W2   16384
#define SM_AS   24576
#define SM_RED  33280
#define SMEM_FLOATS 37632
#define SMEM_BYTES (SMEM_FLOATS * 4)

__global__ __launch_bounds__(NTHR, 1)
void rglstm(const float* __restrict__ W_ih, const float* __restrict__ W_hh,
            const float* __restrict__ b_ih, const float* __restrict__ b_hh,
            const float* __restrict__ W_hg, const float* __restrict__ W_cg,
            const float* __restrict__ eps_h, const float* __restrict__ eps_c,
            float* __restrict__ out)
{
    extern __shared__ float smem[];
    float* sW1 = smem;
    float* sW2 = smem + SM_W2;
    float* As  = smem + SM_AS;
    float* red = smem + SM_RED;

    const int tid = threadIdx.x;
    const int cb  = blockIdx.x;
    const bool isH = cb < 64;
    const int n0_1 = cb << 2;            // stage1: 4 hidden cols (x4 gates)
    const int n0_2 = (cb & 63) << 3;     // stage2: 8 hidden cols (mu+std)

    // compute geometry: 4 K-groups x 64 threads; each 4 rows x 4 cols
    const int g   = tid >> 6;
    const int t64 = tid & 63;
    const int r0  = (t64 >> 2) << 2;     // rows (b)
    const int c0  = (t64 & 3) << 2;      // cols

    // loader geometry: one buffer slot per 4 threads, 16 b each
    const int lslot = tid >> 2;          // 0..63
    const int lb0   = (tid & 3) << 4;

    // ---- persistent weight slices into SMEM ----
    for (int i = tid; i < 16 * 1024; i += NTHR) {
        int c = i >> 10, k = i & 1023;
        int gcol = ((c >> 2) << 9) + n0_1 + (c & 3);
        sW1[k * 16 + c] = (k < 512) ? W_ih[gcol * 512 + k] : W_hh[gcol * 512 + (k - 512)];
    }
    const float* Wg = isH ? W_hg : W_cg;
    for (int i = tid; i < 16 * 512; i += NTHR) {
        int k = i >> 4, c = i & 15;
        int pcol = (c < 8) ? (n0_2 + c) : (512 + n0_2 + (c - 8));
        sW2[k * 16 + c] = Wg[k * 1024 + pcol];
    }

    // epilogue-1 geometry + biases
    const int e_b  = tid & 63;
    const int e_nn = tid >> 6;
    float bias[4];
    #pragma unroll
    for (int gg = 0; gg < 4; ++gg) {
        int gcol = (gg << 9) + n0_1 + e_nn;
        bias[gg] = b_ih[gcol] + b_hh[gcol];
    }
    // epilogue-2 geometry
    const int e2_j  = tid & 7;
    const int e2_b0 = tid >> 3;          // 0..31

    // ---- t=0: z=0 -> mu=1e-6, std=softplus(0)=ln2 ----
    {
        const float LN2 = 0.693147180559945309f;
        int i = cb * NTHR + tid;         // 0..32767 = n*64+b
        int b = i & 63, n = i >> 6;
        g_h[i] = fmaf(eps_h[(size_t)b * 512 + n], LN2, 1e-6f);
        g_c[i] = fmaf(eps_c[(size_t)b * 512 + n], LN2, 1e-6f);
        size_t o = (size_t)b * 262656 + n;
        out[O_HMU  + o] = 1e-6f;
        out[O_HSTD + o] = LN2;
        out[O_CMU  + o] = 1e-6f;
        out[O_CSTD + o] = LN2;
    }
    grid_bar();

    const float* Asrc2  = isH ? g_hn  : g_cn;
    float*       Sdst   = isH ? g_h   : g_c;
    const float* epsP   = isH ? eps_h : eps_c;
    const size_t muB = isH ? O_HMU  : O_CMU;
    const size_t sdB = isH ? O_HSTD : O_CSTD;
    const size_t tB  = isH ? O_HT   : O_CT;

    const int sl_g = lslot >> 4, sl_k = lslot & 15;

    for (int s = 0; s < Sn; ++s) {
        unsigned long long acc[8];

        // ================= stage 1: gates = [x_t | h] @ W^T =================
        #pragma unroll
        for (int i = 0; i < 8; ++i) acc[i] = 0ull;

        float4 pre[4];
        {   // prologue: buffer 0
            int k = sl_g * 256 + sl_k;
            const float* p = (k < 512) ? (g_xT + ((size_t)s * 512 + k) * 64)
                                       : (g_h + (k - 512) * 64);
            #pragma unroll
            for (int j = 0; j < 4; ++j) pre[j] = __ldcg((const float4*)(p + lb0 + 4 * j));
            float* d = As + lslot * 68 + lb0;
            #pragma unroll
            for (int j = 0; j < 4; ++j) *(float4*)(d + 4 * j) = pre[j];
        }
        for (int it = 0; it < 16; ++it) {
            if (it < 15) {
                int k = sl_g * 256 + (it + 1) * 16 + sl_k;
                const float* p = (k < 512) ? (g_xT + ((size_t)s * 512 + k) * 64)
                                           : (g_h + (k - 512) * 64);
                #pragma unroll
                for (int j = 0; j < 4; ++j) pre[j] = __ldcg((const float4*)(p + lb0 + 4 * j));
            }
            __syncthreads();
            const float* bufp = As + (it & 1) * 4352;
            const int kgbase = g * 256 + it * 16;
            #pragma unroll
            for (int kkk = 0; kkk < 16; ++kkk) {
                const float* ap = bufp + (g * 16 + kkk) * 68 + r0;
                ulonglong2 av = *(const ulonglong2*)ap;
                float4 wv = *(const float4*)(sW1 + (kgbase + kkk) * 16 + c0);
                unsigned long long w0 = pack2(wv.x, wv.x), w1 = pack2(wv.y, wv.y);
                unsigned long long w2 = pack2(wv.z, wv.z), w3 = pack2(wv.w, wv.w);
                acc[0] = fma2(av.x, w0, acc[0]); acc[1] = fma2(av.y, w0, acc[1]);
                acc[2] = fma2(av.x, w1, acc[2]); acc[3] = fma2(av.y, w1, acc[3]);
                acc[4] = fma2(av.x, w2, acc[4]); acc[5] = fma2(av.y, w2, acc[5]);
                acc[6] = fma2(av.x, w3, acc[6]); acc[7] = fma2(av.y, w3, acc[7]);
            }
            if (it < 15) {
                float* d = As + ((it + 1) & 1) * 4352 + lslot * 68 + lb0;
                #pragma unroll
                for (int j = 0; j < 4; ++j) *(float4*)(d + 4 * j) = pre[j];
            }
        }
        // partials -> red[g][c][r]
        #pragma unroll
        for (int i = 0; i < 4; ++i) {
            *(unsigned long long*)(red + g * 1088 + (c0 + i) * 68 + r0)     = acc[2 * i];
            *(unsigned long long*)(red + g * 1088 + (c0 + i) * 68 + r0 + 2) = acc[2 * i + 1];
        }
        __syncthreads();
        // LSTM pointwise: one (b, n) per thread
        {
            float gv[4];
            #pragma unroll
            for (int gg = 0; gg < 4; ++gg) {
                int c = (gg << 2) + e_nn;
                gv[gg] = red[c * 68 + e_b] + red[1088 + c * 68 + e_b]
                       + red[2176 + c * 68 + e_b] + red[3264 + c * 68 + e_b] + bias[gg];
            }
            int n = n0_1 + e_nn;
            float cold = __ldcg(&g_c[n * 64 + e_b]);
            float cv = sigm(gv[1]) * cold + sigm(gv[0]) * tanhf(gv[2]);
            float hv = sigm(gv[3]) * tanhf(cv);
            g_cn[n * 64 + e_b] = cv;
            g_hn[n * 64 + e_b] = hv;
        }
        grid_bar();

        // ================= stage 2: p = v @ Wg, sample =================
        #pragma unroll
        for (int i = 0; i < 8; ++i) acc[i] = 0ull;
        {
            int k = sl_g * 128 + sl_k;
            const float* p = Asrc2 + k * 64;
            #pragma unroll
            for (int j = 0; j < 4; ++j) pre[j] = __ldcg((const float4*)(p + lb0 + 4 * j));
            float* d = As + lslot * 68 + lb0;
            #pragma unroll
            for (int j = 0; j < 4; ++j) *(float4*)(d + 4 * j) = pre[j];
        }
        for (int it = 0; it < 8; ++it) {
            if (it < 7) {
                int k = sl_g * 128 + (it + 1) * 16 + sl_k;
                const float* p = Asrc2 + k * 64;
                #pragma unroll
                for (int j = 0; j < 4; ++j) pre[j] = __ldcg((const float4*)(p + lb0 + 4 * j));
            }
            __syncthreads();
            const float* bufp = As + (it & 1) * 4352;
            const int kgbase = g * 128 + it * 16;
            #pragma unroll
            for (int kkk = 0; kkk < 16; ++kkk) {
                const float* ap = bufp + (g * 16 + kkk) * 68 + r0;
                ulonglong2 av = *(const ulonglong2*)ap;
                float4 wv = *(const float4*)(sW2 + (kgbase + kkk) * 16 + c0);
                unsigned long long w0 = pack2(wv.x, wv.x), w1 = pack2(wv.y, wv.y);
                unsigned long long w2 = pack2(wv.z, wv.z), w3 = pack2(wv.w, wv.w);
                acc[0] = fma2(av.x, w0, acc[0]); acc[1] = fma2(av.y, w0, acc[1]);
                acc[2] = fma2(av.x, w1, acc[2]); acc[3] = fma2(av.y, w1, acc[3]);
                acc[4] = fma2(av.x, w2, acc[4]); acc[5] = fma2(av.y, w2, acc[5]);
                acc[6] = fma2(av.x, w3, acc[6]); acc[7] = fma2(av.y, w3, acc[7]);
            }
            if (it < 7) {
                float* d = As + ((it + 1) & 1) * 4352 + lslot * 68 + lb0;
                #pragma unroll
                for (int j = 0; j < 4; ++j) *(float4*)(d + 4 * j) = pre[j];
            }
        }
        #pragma unroll
        for (int i = 0; i < 4; ++i) {
            *(unsigned long long*)(red + g * 1088 + (c0 + i) * 68 + r0)     = acc[2 * i];
            *(unsigned long long*)(red + g * 1088 + (c0 + i) * 68 + r0 + 2) = acc[2 * i + 1];
        }
        __syncthreads();
        // sample epilogue: two (b, n) per thread
        #pragma unroll
        for (int half = 0; half < 2; ++half) {
            int b = e2_b0 + half * 32;
            int cm = e2_j, cs = 8 + e2_j;
            float pm = red[cm * 68 + b] + red[1088 + cm * 68 + b]
                     + red[2176 + cm * 68 + b] + red[3264 + cm * 68 + b];
            float ps = red[cs * 68 + b] + red[1088 + cs * 68 + b]
                     + red[2176 + cs * 68 + b] + red[3264 + cs * 68 + b];
            float mu = fminf(fmaxf(pm, 1e-6f), 1e6f);
            float sd = fmaxf(softplus(ps), 1e-6f);
            int n = n0_2 + e2_j;
            float e = epsP[(size_t)(s + 1) * BH + (size_t)b * 512 + n];
            float smp = fmaf(e, sd, mu);
            Sdst[n * 64 + b] = smp;
            size_t o = (size_t)b * 262656 + (size_t)(s + 1) * 512 + n;
            out[muB + o] = mu;
            out[sdB + o] = sd;
            if (isH) out[O_HID + (size_t)b * 262144 + (size_t)s * 512 + n] = smp;
            if (s == Sn - 1) out[tB + (size_t)b * 512 + n] = smp;
        }
        grid_bar();
    }
}

extern "C" void kernel_launch(void* const* d_in, const int* in_sizes, int n_in,
                              void* d_out, int out_size) {
    (void)in_sizes; (void)n_in; (void)out_size;
    const float* x    = (const float*)d_in[0];
    const float* W_ih = (const float*)d_in[1];
    const float* W_hh = (const float*)d_in[2];
    const float* b_ih = (const float*)d_in[3];
    const float* b_hh = (const float*)d_in[4];
    const float* W_hg = (const float*)d_in[5];
    const float* W_cg = (const float*)d_in[6];
    const float* eps_h = (const float*)d_in[7];
    const float* eps_c = (const float*)d_in[8];
    float* out = (float*)d_out;

    dim3 tg(512, 16, 2), tb(32, 8);
    xT_kernel<<<tg, tb>>>(x);

    cudaFuncSetAttribute(rglstm, cudaFuncAttributeMaxDynamicSharedMemorySize, SMEM_BYTES);
    rglstm<<<NBLK, NTHR, SMEM_BYTES>>>(W_ih, W_hh, b_ih, b_hh,
                                       W_hg, W_cg, eps_h, eps_c, out);
}

// round 4
// speedup vs baseline: 1.8563x; 1.1876x over previous
#include <cuda_runtime.h>
#include <math.h>

#define NBLK 128
#define NTHR 512

#define Bn 64
#define Hn 512
#define Sn 512
#define BH (Bn*Hn)         // 32768

// output section offsets (in floats)
#define O_HID   0ull
#define O_HMU   16777216ull
#define O_HSTD  33587200ull
#define O_CMU   50397184ull
#define O_CSTD  67207168ull
#define O_HT    84017152ull
#define O_CT    84049920ull

// persistent state, all [n][b] transposed (b contiguous)
__device__ float g_h[BH], g_c[BH], g_hn[BH], g_cn[BH];
__device__ float g_xT[(size_t)Sn * 512 * 64];   // [s][k][b]  64MB
__device__ unsigned g_cnt = 0;
__device__ volatile unsigned g_gen = 0;

__device__ __forceinline__ void grid_bar() {
    __syncthreads();
    if (threadIdx.x == 0) {
        __threadfence();
        unsigned gen = g_gen;
        if (atomicAdd(&g_cnt, 1u) == NBLK - 1) {
            g_cnt = 0;
            __threadfence();
            g_gen = gen + 1;
        } else {
            while (g_gen == gen) { }
            __threadfence();
        }
    }
    __syncthreads();
}

__device__ __forceinline__ float sigm(float v) { return 1.0f / (1.0f + expf(-v)); }
__device__ __forceinline__ float softplus(float v) {
    return fmaxf(v, 0.0f) + log1pf(expf(-fabsf(v)));
}

// ---- packed f32x2 helpers (Blackwell FFMA2, PTX-only) ----
__device__ __forceinline__ unsigned long long pack2(float a, float b) {
    unsigned long long r;
    asm("mov.b64 %0, {%1, %2};" : "=l"(r) : "f"(a), "f"(b));
    return r;
}
__device__ __forceinline__ unsigned long long fma2(unsigned long long a,
                                                   unsigned long long b,
                                                   unsigned long long c) {
    unsigned long long d;
    asm("fma.rn.f32x2 %0, %1, %2, %3;" : "=l"(d) : "l"(a), "l"(b), "l"(c));
    return d;
}

// one-time x transpose: x[b][s][k] -> g_xT[s][k][b]
__global__ void xT_kernel(const float* __restrict__ x) {
    __shared__ float t[32][33];
    int s = blockIdx.x, k0 = blockIdx.y << 5, b0 = blockIdx.z << 5;
    int tx = threadIdx.x, ty = threadIdx.y;
    for (int bb = ty; bb < 32; bb += 8)
        t[bb][tx] = x[((size_t)(b0 + bb) * Sn + s) * 512 + k0 + tx];
    __syncthreads();
    for (int kk = ty; kk < 32; kk += 8)
        g_xT[((size_t)s * 512 + k0 + kk) * 64 + b0 + tx] = t[tx][kk];
}

// smem (floats): sW1 16384 | sW2 8192 | As 2*4352 | red 8*1088
#define SM_W2   16384
#define SM_AS   24576
#define SM_RED  33280
#define SMEM_FLOATS 41984
#define SMEM_BYTES (SMEM_FLOATS * 4)

__global__ __launch_bounds__(NTHR, 1)
void rglstm(const float* __restrict__ W_ih, const float* __restrict__ W_hh,
            const float* __restrict__ b_ih, const float* __restrict__ b_hh,
            const float* __restrict__ W_hg, const float* __restrict__ W_cg,
            const float* __restrict__ eps_h, const float* __restrict__ eps_c,
            float* __restrict__ out)
{
    extern __shared__ float smem[];
    float* sW1 = smem;
    float* sW2 = smem + SM_W2;
    float* As  = smem + SM_AS;
    float* red = smem + SM_RED;

    const int tid = threadIdx.x;
    const int cb  = blockIdx.x;
    const bool isH = cb < 64;
    const int n0_1 = cb << 2;            // stage1: 4 hidden cols (x4 gates)
    const int n0_2 = (cb & 63) << 3;     // stage2: 8 hidden cols (mu+std)

    // compute geometry: 8 K-groups x 64 threads; each thread 4 rows x 4 cols
    const int g   = tid >> 6;
    const int t64 = tid & 63;
    const int r0  = (t64 >> 2) << 2;     // rows (b)
    const int c0  = (t64 & 3) << 2;      // cols

    // loader geometry: 64 buffer rows, 8 floats (2 x float4) per thread
    const int lslot = tid >> 3;          // 0..63 (row)
    const int lb0   = (tid & 7) << 3;    // b offset
    const int sl_g  = lslot >> 3, sl_k = lslot & 7;

    // ---- persistent weight slices into SMEM ----
    for (int i = tid; i < 16 * 1024; i += NTHR) {
        int c = i >> 10, k = i & 1023;
        int gcol = ((c >> 2) << 9) + n0_1 + (c & 3);
        sW1[k * 16 + c] = (k < 512) ? W_ih[gcol * 512 + k] : W_hh[gcol * 512 + (k - 512)];
    }
    const float* Wg = isH ? W_hg : W_cg;
    for (int i = tid; i < 16 * 512; i += NTHR) {
        int k = i >> 4, c = i & 15;
        int pcol = (c < 8) ? (n0_2 + c) : (512 + n0_2 + (c - 8));
        sW2[k * 16 + c] = Wg[k * 1024 + pcol];
    }

    // epilogue-1 geometry + biases (threads 0..255 active)
    const int e_b  = tid & 63;
    const int e_nn = (tid >> 6) & 3;
    float bias[4];
    #pragma unroll
    for (int gg = 0; gg < 4; ++gg) {
        int gcol = (gg << 9) + n0_1 + e_nn;
        bias[gg] = b_ih[gcol] + b_hh[gcol];
    }
    // epilogue-2 geometry (all 512 threads: one (b, n) pair each)
    const int e2_j = tid & 7;
    const int e2_b = tid >> 3;           // 0..63

    // ---- t=0: z=0 -> mu=1e-6, std=softplus(0)=ln2 ----
    if (tid < 256) {
        const float LN2 = 0.693147180559945309f;
        int i = cb * 256 + tid;          // 0..32767 = n*64+b
        int b = i & 63, n = i >> 6;
        g_h[i] = fmaf(eps_h[(size_t)b * 512 + n], LN2, 1e-6f);
        g_c[i] = fmaf(eps_c[(size_t)b * 512 + n], LN2, 1e-6f);
        size_t o = (size_t)b * 262656 + n;
        out[O_HMU  + o] = 1e-6f;
        out[O_HSTD + o] = LN2;
        out[O_CMU  + o] = 1e-6f;
        out[O_CSTD + o] = LN2;
    }
    grid_bar();

    const float* Asrc2  = isH ? g_hn  : g_cn;
    float*       Sdst   = isH ? g_h   : g_c;
    const float* epsP   = isH ? eps_h : eps_c;
    const size_t muB = isH ? O_HMU  : O_CMU;
    const size_t sdB = isH ? O_HSTD : O_CSTD;
    const size_t tB  = isH ? O_HT   : O_CT;

    for (int s = 0; s < Sn; ++s) {
        unsigned long long acc[8];

        // ================= stage 1: gates = [x_t | h] @ W^T =================
        #pragma unroll
        for (int i = 0; i < 8; ++i) acc[i] = 0ull;

        float4 pre[2];
        {   // prologue: buffer 0 (k chunk of 8 per group)
            int k = sl_g * 128 + sl_k;
            const float* p = (k < 512) ? (g_xT + ((size_t)s * 512 + k) * 64)
                                       : (g_h + (k - 512) * 64);
            pre[0] = __ldcg((const float4*)(p + lb0));
            pre[1] = __ldcg((const float4*)(p + lb0 + 4));
            float* d = As + lslot * 68 + lb0;
            *(float4*)(d)     = pre[0];
            *(float4*)(d + 4) = pre[1];
        }
        for (int it = 0; it < 16; ++it) {
            if (it < 15) {
                int k = sl_g * 128 + (it + 1) * 8 + sl_k;
                const float* p = (k < 512) ? (g_xT + ((size_t)s * 512 + k) * 64)
                                           : (g_h + (k - 512) * 64);
                pre[0] = __ldcg((const float4*)(p + lb0));
                pre[1] = __ldcg((const float4*)(p + lb0 + 4));
            }
            __syncthreads();
            const float* bufp = As + (it & 1) * 4352;
            const int kgbase = g * 128 + it * 8;
            #pragma unroll
            for (int kkk = 0; kkk < 8; ++kkk) {
                const float* ap = bufp + (g * 8 + kkk) * 68 + r0;
                ulonglong2 av = *(const ulonglong2*)ap;
                float4 wv = *(const float4*)(sW1 + (kgbase + kkk) * 16 + c0);
                unsigned long long w0 = pack2(wv.x, wv.x), w1 = pack2(wv.y, wv.y);
                unsigned long long w2 = pack2(wv.z, wv.z), w3 = pack2(wv.w, wv.w);
                acc[0] = fma2(av.x, w0, acc[0]); acc[1] = fma2(av.y, w0, acc[1]);
                acc[2] = fma2(av.x, w1, acc[2]); acc[3] = fma2(av.y, w1, acc[3]);
                acc[4] = fma2(av.x, w2, acc[4]); acc[5] = fma2(av.y, w2, acc[5]);
                acc[6] = fma2(av.x, w3, acc[6]); acc[7] = fma2(av.y, w3, acc[7]);
            }
            if (it < 15) {
                float* d = As + ((it + 1) & 1) * 4352 + lslot * 68 + lb0;
                *(float4*)(d)     = pre[0];
                *(float4*)(d + 4) = pre[1];
            }
        }
        // partials -> red[g][c][r]
        #pragma unroll
        for (int i = 0; i < 4; ++i) {
            *(unsigned long long*)(red + g * 1088 + (c0 + i) * 68 + r0)     = acc[2 * i];
            *(unsigned long long*)(red + g * 1088 + (c0 + i) * 68 + r0 + 2) = acc[2 * i + 1];
        }
        __syncthreads();
        // LSTM pointwise: one (b, n) per thread (threads 0..255)
        if (tid < 256) {
            float gv[4];
            #pragma unroll
            for (int gg = 0; gg < 4; ++gg) {
                int c = (gg << 2) + e_nn;
                float v = bias[gg];
                #pragma unroll
                for (int gp = 0; gp < 8; ++gp)
                    v += red[gp * 1088 + c * 68 + e_b];
                gv[gg] = v;
            }
            int n = n0_1 + e_nn;
            float cold = __ldcg(&g_c[n * 64 + e_b]);
            float cv = sigm(gv[1]) * cold + sigm(gv[0]) * tanhf(gv[2]);
            float hv = sigm(gv[3]) * tanhf(cv);
            g_cn[n * 64 + e_b] = cv;
            g_hn[n * 64 + e_b] = hv;
        }
        grid_bar();

        // ================= stage 2: p = v @ Wg, sample =================
        #pragma unroll
        for (int i = 0; i < 8; ++i) acc[i] = 0ull;
        {
            int k = sl_g * 64 + sl_k;
            const float* p = Asrc2 + k * 64;
            pre[0] = __ldcg((const float4*)(p + lb0));
            pre[1] = __ldcg((const float4*)(p + lb0 + 4));
            float* d = As + lslot * 68 + lb0;
            *(float4*)(d)     = pre[0];
            *(float4*)(d + 4) = pre[1];
        }
        for (int it = 0; it < 8; ++it) {
            if (it < 7) {
                int k = sl_g * 64 + (it + 1) * 8 + sl_k;
                const float* p = Asrc2 + k * 64;
                pre[0] = __ldcg((const float4*)(p + lb0));
                pre[1] = __ldcg((const float4*)(p + lb0 + 4));
            }
            __syncthreads();
            const float* bufp = As + (it & 1) * 4352;
            const int kgbase = g * 64 + it * 8;
            #pragma unroll
            for (int kkk = 0; kkk < 8; ++kkk) {
                const float* ap = bufp + (g * 8 + kkk) * 68 + r0;
                ulonglong2 av = *(const ulonglong2*)ap;
                float4 wv = *(const float4*)(sW2 + (kgbase + kkk) * 16 + c0);
                unsigned long long w0 = pack2(wv.x, wv.x), w1 = pack2(wv.y, wv.y);
                unsigned long long w2 = pack2(wv.z, wv.z), w3 = pack2(wv.w, wv.w);
                acc[0] = fma2(av.x, w0, acc[0]); acc[1] = fma2(av.y, w0, acc[1]);
                acc[2] = fma2(av.x, w1, acc[2]); acc[3] = fma2(av.y, w1, acc[3]);
                acc[4] = fma2(av.x, w2, acc[4]); acc[5] = fma2(av.y, w2, acc[5]);
                acc[6] = fma2(av.x, w3, acc[6]); acc[7] = fma2(av.y, w3, acc[7]);
            }
            if (it < 7) {
                float* d = As + ((it + 1) & 1) * 4352 + lslot * 68 + lb0;
                *(float4*)(d)     = pre[0];
                *(float4*)(d + 4) = pre[1];
            }
        }
        #pragma unroll
        for (int i = 0; i < 4; ++i) {
            *(unsigned long long*)(red + g * 1088 + (c0 + i) * 68 + r0)     = acc[2 * i];
            *(unsigned long long*)(red + g * 1088 + (c0 + i) * 68 + r0 + 2) = acc[2 * i + 1];
        }
        __syncthreads();
        // sample epilogue: one (b, n) per thread
        {
            int b = e2_b;
            int cm = e2_j, cs = 8 + e2_j;
            float pm = 0.f, ps = 0.f;
            #pragma unroll
            for (int gp = 0; gp < 8; ++gp) {
                pm += red[gp * 1088 + cm * 68 + b];
                ps += red[gp * 1088 + cs * 68 + b];
            }
            float mu = fminf(fmaxf(pm, 1e-6f), 1e6f);
            float sd = fmaxf(softplus(ps), 1e-6f);
            int n = n0_2 + e2_j;
            float e = epsP[(size_t)(s + 1) * BH + (size_t)b * 512 + n];
            float smp = fmaf(e, sd, mu);
            Sdst[n * 64 + b] = smp;
            size_t o = (size_t)b * 262656 + (size_t)(s + 1) * 512 + n;
            out[muB + o] = mu;
            out[sdB + o] = sd;
            if (isH) out[O_HID + (size_t)b * 262144 + (size_t)s * 512 + n] = smp;
            if (s == Sn - 1) out[tB + (size_t)b * 512 + n] = smp;
        }
        grid_bar();
    }
}

extern "C" void kernel_launch(void* const* d_in, const int* in_sizes, int n_in,
                              void* d_out, int out_size) {
    (void)in_sizes; (void)n_in; (void)out_size;
    const float* x    = (const float*)d_in[0];
    const float* W_ih = (const float*)d_in[1];
    const float* W_hh = (const float*)d_in[2];
    const float* b_ih = (const float*)d_in[3];
    const float* b_hh = (const float*)d_in[4];
    const float* W_hg = (const float*)d_in[5];
    const float* W_cg = (const float*)d_in[6];
    const float* eps_h = (const float*)d_in[7];
    const float* eps_c = (const float*)d_in[8];
    float* out = (float*)d_out;

    dim3 tg(512, 16, 2), tb(32, 8);
    xT_kernel<<<tg, tb>>>(x);

    cudaFuncSetAttribute(rglstm, cudaFuncAttributeMaxDynamicSharedMemorySize, SMEM_BYTES);
    rglstm<<<NBLK, NTHR, SMEM_BYTES>>>(W_ih, W_hh, b_ih, b_hh,
                                       W_hg, W_cg, eps_h, eps_c, out);
}